// round 6
// baseline (speedup 1.0000x reference)
#include <cuda_runtime.h>
#include <cstdint>

// ---------------- problem constants ----------------
#define HH 128
#define WW 128
#define CIN 256
#define NPIX (HH*WW)            // 16384
#define NA 9
#define NANCH (NPIX*NA)         // 147456
#define PRE_K 6000
#define POST_K 300
#define NWORDS 94               // ceil(6000/64)
#define SORT_N 8192
#define DW_CLIP_F 4.135166556742356f
#define IMSZ 1024.0f

// ---------------- device scratch ----------------
__device__ float g_rpnfeat[CIN*NPIX];                 // 16.8 MB
__device__ float g_scores[NANCH];
__device__ float g_props[NANCH*4];
__device__ unsigned int g_hist[256];
__device__ unsigned int g_state[2];                   // [0]=prefix, [1]=kneed
__device__ unsigned int g_selcnt;
__device__ unsigned long long g_sel[SORT_N];
__device__ float g_b6[PRE_K*4];
__device__ float g_s6[PRE_K];
__device__ unsigned char g_valid[PRE_K];
__device__ unsigned long long g_mask[PRE_K*NWORDS];   // 4.5 MB
__device__ unsigned char g_keep[PRE_K];

// ---------------- K1: 3x3 conv + bias + relu (implicit GEMM) ----------------
// grid(256, 4): blockIdx.x -> (y, half-row), blockIdx.y -> 64-out-channel tile
__global__ __launch_bounds__(256) void conv3_kernel(const float* __restrict__ feat,
                                                    const float* __restrict__ wt,
                                                    const float* __restrict__ bias)
{
    __shared__ float As[8*3*68];   // [ci][row y-1..y+1][x0-1 .. x0+64] padded to 68
    __shared__ float Ws[72*64];    // [(ci*9+tap)][co_local]

    const int tid = threadIdx.x;
    const int tx = tid & 15, ty = tid >> 4;
    const int tx4 = tx*4, ty4 = ty*4;
    const int bx = blockIdx.x;
    const int y  = bx >> 1;
    const int x0 = (bx & 1) * 64;
    const int co0 = blockIdx.y * 64;

    float acc[4][4];
#pragma unroll
    for (int r=0;r<4;r++)
#pragma unroll
        for (int c=0;c<4;c++) acc[r][c]=0.f;

    for (int ci0 = 0; ci0 < CIN; ci0 += 8) {
        __syncthreads();
        // input halo tile: 8 ci x 3 rows x 66 x
        for (int e = tid; e < 8*3*66; e += 256) {
            int ci = e / (3*66);
            int rr = e % (3*66);
            int r  = rr / 66;
            int xi = rr % 66;
            int yy = y + r - 1;
            int xx = x0 + xi - 1;
            float v = 0.f;
            if (yy >= 0 && yy < HH && xx >= 0 && xx < WW)
                v = feat[(ci0+ci)*NPIX + yy*WW + xx];
            As[(ci*3+r)*68 + xi] = v;
        }
        // weights: thread -> (co_l = tid>>2, sub = tid&3), 18 contiguous taps each
        {
            int co_l = tid >> 2, sub = tid & 3;
            const float* wsrc = wt + ((size_t)(co0+co_l)*CIN + ci0)*9 + sub*18;
#pragma unroll
            for (int q = 0; q < 18; q++) {
                int kt = sub*18 + q;
                Ws[kt*64 + co_l] = wsrc[q];
            }
        }
        __syncthreads();

#pragma unroll
        for (int ky = 0; ky < 3; ky++) {
#pragma unroll
            for (int kx = 0; kx < 3; kx++) {
                const int tap = ky*3 + kx;
#pragma unroll
                for (int ci = 0; ci < 8; ci++) {
                    const float4 av = *(const float4*)&Ws[(ci*9+tap)*64 + ty4];
                    const float* bp = &As[(ci*3+ky)*68 + tx4 + kx];
                    const float b0 = bp[0], b1 = bp[1], b2 = bp[2], b3 = bp[3];
                    acc[0][0] += av.x*b0; acc[0][1] += av.x*b1; acc[0][2] += av.x*b2; acc[0][3] += av.x*b3;
                    acc[1][0] += av.y*b0; acc[1][1] += av.y*b1; acc[1][2] += av.y*b2; acc[1][3] += av.y*b3;
                    acc[2][0] += av.z*b0; acc[2][1] += av.z*b1; acc[2][2] += av.z*b2; acc[2][3] += av.z*b3;
                    acc[3][0] += av.w*b0; acc[3][1] += av.w*b1; acc[3][2] += av.w*b2; acc[3][3] += av.w*b3;
                }
            }
        }
    }

#pragma unroll
    for (int r = 0; r < 4; r++) {
        const int co = co0 + ty4 + r;
        const float bv = bias[co];
#pragma unroll
        for (int c = 0; c < 4; c++) {
            float v = acc[r][c] + bv;
            g_rpnfeat[co*NPIX + y*WW + x0 + tx4 + c] = fmaxf(v, 0.f);
        }
    }
}

// ---------------- K2: 1x1 heads (45 ch) + anchor decode + sigmoid ----------------
// grid(256): 64 pixels per block. threads: px = tid&63, grp = tid>>6 (12 ch each)
__global__ __launch_bounds__(256) void head_kernel(const float* __restrict__ clsw,
                                                   const float* __restrict__ clsb,
                                                   const float* __restrict__ boxw,
                                                   const float* __restrict__ boxb)
{
    __shared__ float Ft[32*64];
    __shared__ float Wc[32*48];
    __shared__ float st[64*48];

    const int tid = threadIdx.x;
    const int p0 = blockIdx.x * 64;
    const int px = tid & 63, g = tid >> 6;

    float acc[12];
#pragma unroll
    for (int j=0;j<12;j++) acc[j]=0.f;

    for (int c0 = 0; c0 < CIN; c0 += 32) {
        __syncthreads();
        for (int e = tid; e < 32*64; e += 256) {
            int ci = e >> 6, pp = e & 63;
            Ft[e] = g_rpnfeat[(c0+ci)*NPIX + p0 + pp];
        }
        for (int e = tid; e < 32*45; e += 256) {
            int ci = e / 45, ch = e % 45;
            float v = (ch < 9) ? clsw[ch*CIN + c0 + ci] : boxw[(ch-9)*CIN + c0 + ci];
            Wc[ci*48 + ch] = v;
        }
        __syncthreads();
#pragma unroll 8
        for (int ci = 0; ci < 32; ci++) {
            float f = Ft[ci*64 + px];
#pragma unroll
            for (int j = 0; j < 12; j++)
                acc[j] += Wc[ci*48 + g*12 + j] * f;
        }
    }
    __syncthreads();
#pragma unroll
    for (int j = 0; j < 12; j++) {
        int ch = g*12 + j;
        if (ch < 45) st[px*48 + ch] = acc[j];
    }
    __syncthreads();

    for (int t2 = tid; t2 < 64*9; t2 += 256) {
        const int a = t2 % 9, pp = t2 / 9;
        const int p = p0 + pp;
        const int yy = p >> 7, xx = p & 127;

        float cls = st[pp*48 + a] + clsb[a];
        float d0 = st[pp*48 + 9 + a*4 + 0] + boxb[a*4+0];
        float d1 = st[pp*48 + 9 + a*4 + 1] + boxb[a*4+1];
        float d2 = st[pp*48 + 9 + a*4 + 2] + boxb[a*4+2];
        float d3 = st[pp*48 + 9 + a*4 + 3] + boxb[a*4+3];

        // base anchor (bit-replicates reference fp32 math)
        const int iar = a / 3, jsc = a % 3;
        const float ar = (iar==0) ? 0.5f : (iar==1 ? 1.0f : 2.0f);
        const float sc = (jsc==0) ? 128.f : (jsc==1 ? 256.f : 512.f);
        const float hr = sqrtf(ar);
        const float wr = 1.0f / hr;
        const float hs = hr * sc, ws = wr * sc;
        const float bx1 = rintf(-ws*0.5f), by1 = rintf(-hs*0.5f);
        const float bx2 = rintf( ws*0.5f), by2 = rintf( hs*0.5f);
        const float ax1 = xx*8.0f + bx1, ay1 = yy*8.0f + by1;
        const float ax2 = xx*8.0f + bx2, ay2 = yy*8.0f + by2;

        const float w  = ax2 - ax1, h = ay2 - ay1;
        const float cx = ax1 + 0.5f*w, cy = ay1 + 0.5f*h;
        const float dw = fminf(d2, DW_CLIP_F);
        const float dh = fminf(d3, DW_CLIP_F);
        const float pcx = d0*w + cx, pcy = d1*h + cy;
        const float pw = expf(dw)*w, ph = expf(dh)*h;

        const int n = p*9 + a;
        g_props[n*4+0] = pcx - 0.5f*pw;
        g_props[n*4+1] = pcy - 0.5f*ph;
        g_props[n*4+2] = pcx + 0.5f*pw;
        g_props[n*4+3] = pcy + 0.5f*ph;
        g_scores[n] = 1.0f / (1.0f + expf(-cls));
    }
}

// ---------------- K3: exact top-6000 via 4-pass radix select ----------------
__global__ void topk_init()
{
    int i = blockIdx.x*blockDim.x + threadIdx.x;
    if (i < SORT_N) g_sel[i] = ~0ull;
    if (i < 256) g_hist[i] = 0u;
    if (i == 0) { g_state[0] = 0u; g_state[1] = PRE_K; g_selcnt = 0u; }
}

__global__ __launch_bounds__(256) void topk_hist(int pass, int shift)
{
    __shared__ unsigned int sh[256];
    const int tid = threadIdx.x;
    sh[tid] = 0u;
    __syncthreads();
    int i = blockIdx.x*256 + tid;
    if (i < NANCH) {
        unsigned int key = __float_as_uint(g_scores[i]);
        bool ok = (pass == 0) || ((key >> (shift+8)) == g_state[0]);
        if (ok) atomicAdd(&sh[(key >> shift) & 255], 1u);
    }
    __syncthreads();
    if (sh[tid]) atomicAdd(&g_hist[tid], sh[tid]);
}

__global__ void topk_select()
{
    if (threadIdx.x == 0) {
        unsigned int kneed = g_state[1];
        unsigned int cum = 0; int chosen = 0;
        for (int d = 255; d >= 0; d--) {
            unsigned int c = g_hist[d];
            if (cum + c >= kneed) { chosen = d; break; }
            cum += c;
        }
        g_state[0] = (g_state[0] << 8) | (unsigned int)chosen;
        g_state[1] = kneed - cum;
    }
    __syncthreads();
    g_hist[threadIdx.x] = 0u;     // 256 threads
}

__global__ __launch_bounds__(256) void topk_compact()
{
    int i = blockIdx.x*256 + threadIdx.x;
    if (i >= NANCH) return;
    unsigned int key = __float_as_uint(g_scores[i]);
    unsigned int T = g_state[0];
    if (key >= T) {
        unsigned int pos = atomicAdd(&g_selcnt, 1u);
        if (pos < SORT_N)
            g_sel[pos] = ((unsigned long long)(~key) << 32) | (unsigned int)i;
    }
}

// sort 8192 64-bit keys ascending ((~scorebits)<<32 | idx) -> score desc, idx asc
__global__ __launch_bounds__(1024) void topk_sort()
{
    extern __shared__ unsigned long long S[];
    const int tid = threadIdx.x;
    for (int k = tid; k < SORT_N; k += 1024) S[k] = g_sel[k];
    __syncthreads();
    for (int k = 2; k <= SORT_N; k <<= 1) {
        for (int j = k >> 1; j > 0; j >>= 1) {
            for (int t = tid; t < SORT_N; t += 1024) {
                int ixj = t ^ j;
                if (ixj > t) {
                    unsigned long long a = S[t], b = S[ixj];
                    bool up = (t & k) == 0;
                    if ((a > b) == up) { S[t] = b; S[ixj] = a; }
                }
            }
            __syncthreads();
        }
    }
    for (int k = tid; k < PRE_K; k += 1024) g_sel[k] = S[k];
}

// ---------------- K4: gather + clip + min-size validity ----------------
__global__ __launch_bounds__(256) void prep_kernel()
{
    int i = blockIdx.x*256 + threadIdx.x;
    if (i >= PRE_K) return;
    unsigned long long sel = g_sel[i];
    unsigned int idx = (unsigned int)(sel & 0xffffffffull);
    unsigned int kb = ~(unsigned int)(sel >> 32);
    float scv = __uint_as_float(kb);
    float x1 = g_props[idx*4+0], y1 = g_props[idx*4+1];
    float x2 = g_props[idx*4+2], y2 = g_props[idx*4+3];
    x1 = fminf(fmaxf(x1, 0.f), IMSZ);
    y1 = fminf(fmaxf(y1, 0.f), IMSZ);
    x2 = fminf(fmaxf(x2, 0.f), IMSZ);
    y2 = fminf(fmaxf(y2, 0.f), IMSZ);
    g_b6[i*4+0] = x1; g_b6[i*4+1] = y1; g_b6[i*4+2] = x2; g_b6[i*4+3] = y2;
    g_s6[i] = scv;
    g_valid[i] = ((x2 - x1) >= 16.f && (y2 - y1) >= 16.f) ? 1 : 0;
}

// ---------------- K5: NMS suppression bitmask ----------------
// grid(94 rowblocks, 94 colblocks), 64 threads: thread = row i, word = colblock
__global__ __launch_bounds__(64) void nms_mask_kernel()
{
    const int rb = blockIdx.x, cb = blockIdx.y;
    const int tid = threadIdx.x;
    __shared__ float cbx1[64], cby1[64], cbx2[64], cby2[64];
    const int j0 = cb*64;
    {
        int j = j0 + tid;
        float a=0,b=0,c=0,d=0;
        if (j < PRE_K) { a=g_b6[j*4+0]; b=g_b6[j*4+1]; c=g_b6[j*4+2]; d=g_b6[j*4+3]; }
        cbx1[tid]=a; cby1[tid]=b; cbx2[tid]=c; cby2[tid]=d;
    }
    __syncthreads();
    const int i = rb*64 + tid;
    if (i >= PRE_K) return;
    if (cb < rb) { g_mask[i*NWORDS + cb] = 0ull; return; }

    const float ix1 = g_b6[i*4+0], iy1 = g_b6[i*4+1];
    const float ix2 = g_b6[i*4+2], iy2 = g_b6[i*4+3];
    const float ai = (ix2-ix1)*(iy2-iy1);
    unsigned long long bits = 0ull;
#pragma unroll 4
    for (int jj = 0; jj < 64; jj++) {
        const int j = j0 + jj;
        if (j <= i || j >= PRE_K) continue;
        float xx1 = fmaxf(ix1, cbx1[jj]);
        float yy1 = fmaxf(iy1, cby1[jj]);
        float xx2 = fminf(ix2, cbx2[jj]);
        float yy2 = fminf(iy2, cby2[jj]);
        float inter = fmaxf(xx2-xx1, 0.f) * fmaxf(yy2-yy1, 0.f);
        float aj = (cbx2[jj]-cbx1[jj])*(cby2[jj]-cby1[jj]);
        float iou = inter / (ai + aj - inter);
        if (iou > 0.7f) bits |= (1ull << jj);
    }
    g_mask[i*NWORDS + cb] = bits;
}

// ---------------- K6: greedy serial scan (1 warp, depth-8 row prefetch) ----------------
__global__ __launch_bounds__(32) void nms_scan_kernel()
{
    const int l = threadIdx.x;
    unsigned long long rem0 = 0ull, rem1 = 0ull, rem2 = 0ull;

    // initialize removal bits from invalid boxes
#pragma unroll
    for (int s = 0; s < 3; s++) {
        int w = l + 32*s;
        unsigned long long v = 0ull;
        if (w < NWORDS) {
            for (int b = 0; b < 64; b++) {
                int i = w*64 + b;
                if (i < PRE_K && g_valid[i] == 0) v |= (1ull << b);
            }
        }
        if (s == 0) rem0 = v; else if (s == 1) rem1 = v; else rem2 = v;
    }

    unsigned long long pa[8], pb[8], pc[8];
#pragma unroll
    for (int b = 0; b < 8; b++) {
        const unsigned long long* row = g_mask + (size_t)b*NWORDS;
        pa[b] = row[l];
        pb[b] = (l + 32 < NWORDS) ? row[l+32] : 0ull;
        pc[b] = (l < NWORDS - 64) ? row[l+64] : 0ull;
    }

    for (int i0 = 0; i0 < PRE_K; i0 += 8) {
#pragma unroll
        for (int u = 0; u < 8; u++) {
            const int i = i0 + u;
            const int w = i >> 6;
            const int src = w & 31;
            const int slot = w >> 5;
            unsigned long long myword = (slot == 0) ? rem0 : ((slot == 1) ? rem1 : rem2);
            unsigned long long word = __shfl_sync(0xffffffffu, myword, src);
            const bool sup = (word >> (i & 63)) & 1ull;
            if (!sup) { rem0 |= pa[u]; rem1 |= pb[u]; rem2 |= pc[u]; }
            if (l == 0) g_keep[i] = sup ? 0 : 1;
            const int nx = i + 8;
            if (nx < PRE_K) {
                const unsigned long long* row = g_mask + (size_t)nx*NWORDS;
                pa[u] = row[l];
                pb[u] = (l + 32 < NWORDS) ? row[l+32] : 0ull;
                pc[u] = (l < NWORDS - 64) ? row[l+64] : 0ull;
            }
        }
    }
}

// ---------------- K7: compact first 300 kept (already score-sorted) ----------------
__global__ __launch_bounds__(256) void out_kernel(float* __restrict__ out)
{
    const int tid = threadIdx.x;
    for (int k = tid; k < POST_K*5; k += 256) out[k] = 0.f;
    __shared__ int cnts[256];
    __shared__ int offs[256];
    int c = 0;
    if (tid < 250) {
        for (int j = 0; j < 24; j++) c += g_keep[tid*24 + j];
    }
    cnts[tid] = c;
    __syncthreads();
    if (tid == 0) {
        int s = 0;
        for (int t = 0; t < 250; t++) { offs[t] = s; s += cnts[t]; }
    }
    __syncthreads();
    if (tid < 250) {
        int r = offs[tid];
        for (int j = 0; j < 24; j++) {
            int i = tid*24 + j;
            if (g_keep[i]) {
                if (r < POST_K) {
                    out[r*5+0] = g_b6[i*4+0];
                    out[r*5+1] = g_b6[i*4+1];
                    out[r*5+2] = g_b6[i*4+2];
                    out[r*5+3] = g_b6[i*4+3];
                    out[r*5+4] = g_s6[i];
                }
                r++;
            }
        }
    }
}

// ---------------- launch ----------------
extern "C" void kernel_launch(void* const* d_in, const int* in_sizes, int n_in,
                              void* d_out, int out_size)
{
    (void)in_sizes; (void)n_in; (void)out_size;
    const float* feat = (const float*)d_in[1];
    const float* cw   = (const float*)d_in[2];
    const float* cb   = (const float*)d_in[3];
    const float* clsw = (const float*)d_in[4];
    const float* clsb = (const float*)d_in[5];
    const float* bw   = (const float*)d_in[6];
    const float* bb   = (const float*)d_in[7];
    float* out = (float*)d_out;

    conv3_kernel<<<dim3(256, 4), 256>>>(feat, cw, cb);
    head_kernel<<<256, 256>>>(clsw, clsb, bw, bb);

    topk_init<<<32, 256>>>();
    topk_hist<<<576, 256>>>(0, 24); topk_select<<<1, 256>>>();
    topk_hist<<<576, 256>>>(1, 16); topk_select<<<1, 256>>>();
    topk_hist<<<576, 256>>>(2, 8);  topk_select<<<1, 256>>>();
    topk_hist<<<576, 256>>>(3, 0);  topk_select<<<1, 256>>>();
    topk_compact<<<576, 256>>>();

    cudaFuncSetAttribute(topk_sort, cudaFuncAttributeMaxDynamicSharedMemorySize, 65536);
    topk_sort<<<1, 1024, 65536>>>();

    prep_kernel<<<24, 256>>>();
    nms_mask_kernel<<<dim3(94, 94), 64>>>();
    nms_scan_kernel<<<1, 32>>>();
    out_kernel<<<1, 256>>>(out);
}

// round 7
// speedup vs baseline: 1.1029x; 1.1029x over previous
#include <cuda_runtime.h>
#include <cstdint>

// ---------------- problem constants ----------------
#define HH 128
#define WW 128
#define CIN 256
#define NPIX (HH*WW)            // 16384
#define NA 9
#define NANCH (NPIX*NA)         // 147456
#define PRE_K 6000
#define POST_K 300
#define NWORDS 94               // ceil(6000/64)
#define SORT_N 8192
#define DW_CLIP_F 4.135166556742356f
#define IMSZ 1024.0f

// packed fp32x2 helpers (sm_100+): bit-identical IEEE fp32 RN, 2x fma throughput
#define FMA2(d,a,b) asm("fma.rn.f32x2 %0, %1, %2, %0;" : "+l"(d) : "l"(a), "l"(b))
#define PACK2(d,s)  asm("mov.b64 %0, {%1, %1};" : "=l"(d) : "f"(s))
#define UNPACK2(lo,hi,v) asm("mov.b64 {%0, %1}, %2;" : "=f"(lo), "=f"(hi) : "l"(v))

// ---------------- device scratch ----------------
__device__ float g_rpnfeat[CIN*NPIX];                 // 16.8 MB
__device__ float g_scores[NANCH];
__device__ float g_props[NANCH*4];
__device__ unsigned int g_hist[256];
__device__ unsigned int g_state[2];                   // [0]=prefix, [1]=kneed
__device__ unsigned int g_selcnt;
__device__ unsigned long long g_sel[SORT_N];
__device__ float g_b6[PRE_K*4];
__device__ float g_s6[PRE_K];
__device__ unsigned char g_valid[PRE_K];
__device__ unsigned long long g_mask[PRE_K*NWORDS];   // 4.5 MB
__device__ unsigned char g_keep[PRE_K];

// ---------------- K1: 3x3 conv + bias + relu (implicit GEMM, f32x2) ----------------
// block = 128 threads. tile = 64 co x 64 px (one y row, half x).
// thread tile = 8 co x 4 px, accumulated as 16 f32x2 pairs (pair dim = co).
// grid(256, 4): blockIdx.x -> (y, half-row), blockIdx.y -> 64-out-channel tile
__global__ __launch_bounds__(128) void conv3_kernel(const float* __restrict__ feat,
                                                    const float* __restrict__ wt,
                                                    const float* __restrict__ bias)
{
    __shared__ __align__(16) float As[8*3*68];   // [ci][row y-1..y+1][xi 0..65], pad 68
    __shared__ __align__(16) float Ws[72*64];    // [(ci*9+tap)][co_local]

    const int tid = threadIdx.x;
    const int tx  = tid & 15;          // px group
    const int ty  = tid >> 4;          // co group (0..7)
    const int px4 = tx * 4;
    const int co8 = ty * 8;
    const int bx = blockIdx.x;
    const int y  = bx >> 1;
    const int x0 = (bx & 1) * 64;
    const int co0 = blockIdx.y * 64;

    unsigned long long acc[16];        // [rp][c] rp=co-pair 0..3, c=px 0..3
#pragma unroll
    for (int i = 0; i < 16; i++) acc[i] = 0ull;

    for (int ci0 = 0; ci0 < CIN; ci0 += 8) {
        __syncthreads();
        // input halo tile: 8 ci x 3 rows x 66 x (zero padded borders)
        for (int e = tid; e < 8*3*66; e += 128) {
            int ci = e / (3*66);
            int rr = e % (3*66);
            int r  = rr / 66;
            int xi = rr % 66;
            int yy = y + r - 1;
            int xx = x0 + xi - 1;
            float v = 0.f;
            if (yy >= 0 && yy < HH && xx >= 0 && xx < WW)
                v = feat[(ci0+ci)*NPIX + yy*WW + xx];
            As[(ci*3+r)*68 + xi] = v;
        }
        // weights: 2 threads per co_local, 36 contiguous taps each
        {
            int co_l = tid >> 1, sub = tid & 1;
            const float* wsrc = wt + ((size_t)(co0+co_l)*CIN + ci0)*9 + sub*36;
#pragma unroll
            for (int q = 0; q < 36; q++)
                Ws[(sub*36 + q)*64 + co_l] = wsrc[q];
        }
        __syncthreads();

#pragma unroll
        for (int ci = 0; ci < 8; ci++) {
#pragma unroll
            for (int ky = 0; ky < 3; ky++) {
                const int rowb = (ci*3+ky)*68 + px4;
                const float4 blo = *(const float4*)&As[rowb];
                const float4 bhi = *(const float4*)&As[rowb + 4];
                unsigned long long pb[6];
                PACK2(pb[0], blo.x); PACK2(pb[1], blo.y); PACK2(pb[2], blo.z);
                PACK2(pb[3], blo.w); PACK2(pb[4], bhi.x); PACK2(pb[5], bhi.y);
#pragma unroll
                for (int kx = 0; kx < 3; kx++) {
                    const ulonglong2* wp =
                        (const ulonglong2*)&Ws[(ci*9 + ky*3 + kx)*64 + co8];
                    const ulonglong2 w0 = wp[0];
                    const ulonglong2 w1 = wp[1];
#pragma unroll
                    for (int c = 0; c < 4; c++) {
                        FMA2(acc[0*4+c], w0.x, pb[kx+c]);
                        FMA2(acc[1*4+c], w0.y, pb[kx+c]);
                        FMA2(acc[2*4+c], w1.x, pb[kx+c]);
                        FMA2(acc[3*4+c], w1.y, pb[kx+c]);
                    }
                }
            }
        }
    }

#pragma unroll
    for (int rp = 0; rp < 4; rp++) {
        const int coA = co0 + co8 + rp*2;
        const int coB = coA + 1;
        const float bA = bias[coA];
        const float bB = bias[coB];
#pragma unroll
        for (int c = 0; c < 4; c++) {
            float lo, hi;
            UNPACK2(lo, hi, acc[rp*4+c]);
            const int p = y*WW + x0 + px4 + c;
            g_rpnfeat[coA*NPIX + p] = fmaxf(lo + bA, 0.f);
            g_rpnfeat[coB*NPIX + p] = fmaxf(hi + bB, 0.f);
        }
    }
}

// ---------------- K2: 1x1 heads (45 ch) + anchor decode + sigmoid ----------------
// grid(256): 64 pixels per block. threads: px = tid&63, grp = tid>>6 (12 ch each)
__global__ __launch_bounds__(256) void head_kernel(const float* __restrict__ clsw,
                                                   const float* __restrict__ clsb,
                                                   const float* __restrict__ boxw,
                                                   const float* __restrict__ boxb)
{
    __shared__ float Ft[32*64];
    __shared__ float Wc[32*48];
    __shared__ float st[64*48];

    const int tid = threadIdx.x;
    const int p0 = blockIdx.x * 64;
    const int px = tid & 63, g = tid >> 6;

    float acc[12];
#pragma unroll
    for (int j=0;j<12;j++) acc[j]=0.f;

    for (int c0 = 0; c0 < CIN; c0 += 32) {
        __syncthreads();
        for (int e = tid; e < 32*64; e += 256) {
            int ci = e >> 6, pp = e & 63;
            Ft[e] = g_rpnfeat[(c0+ci)*NPIX + p0 + pp];
        }
        for (int e = tid; e < 32*45; e += 256) {
            int ci = e / 45, ch = e % 45;
            float v = (ch < 9) ? clsw[ch*CIN + c0 + ci] : boxw[(ch-9)*CIN + c0 + ci];
            Wc[ci*48 + ch] = v;
        }
        __syncthreads();
#pragma unroll 8
        for (int ci = 0; ci < 32; ci++) {
            float f = Ft[ci*64 + px];
#pragma unroll
            for (int j = 0; j < 12; j++)
                acc[j] += Wc[ci*48 + g*12 + j] * f;
        }
    }
    __syncthreads();
#pragma unroll
    for (int j = 0; j < 12; j++) {
        int ch = g*12 + j;
        if (ch < 45) st[px*48 + ch] = acc[j];
    }
    __syncthreads();

    for (int t2 = tid; t2 < 64*9; t2 += 256) {
        const int a = t2 % 9, pp = t2 / 9;
        const int p = p0 + pp;
        const int yy = p >> 7, xx = p & 127;

        float cls = st[pp*48 + a] + clsb[a];
        float d0 = st[pp*48 + 9 + a*4 + 0] + boxb[a*4+0];
        float d1 = st[pp*48 + 9 + a*4 + 1] + boxb[a*4+1];
        float d2 = st[pp*48 + 9 + a*4 + 2] + boxb[a*4+2];
        float d3 = st[pp*48 + 9 + a*4 + 3] + boxb[a*4+3];

        // base anchor (bit-replicates reference fp32 math)
        const int iar = a / 3, jsc = a % 3;
        const float ar = (iar==0) ? 0.5f : (iar==1 ? 1.0f : 2.0f);
        const float sc = (jsc==0) ? 128.f : (jsc==1 ? 256.f : 512.f);
        const float hr = sqrtf(ar);
        const float wr = 1.0f / hr;
        const float hs = hr * sc, ws = wr * sc;
        const float bx1 = rintf(-ws*0.5f), by1 = rintf(-hs*0.5f);
        const float bx2 = rintf( ws*0.5f), by2 = rintf( hs*0.5f);
        const float ax1 = xx*8.0f + bx1, ay1 = yy*8.0f + by1;
        const float ax2 = xx*8.0f + bx2, ay2 = yy*8.0f + by2;

        const float w  = ax2 - ax1, h = ay2 - ay1;
        const float cx = ax1 + 0.5f*w, cy = ay1 + 0.5f*h;
        const float dw = fminf(d2, DW_CLIP_F);
        const float dh = fminf(d3, DW_CLIP_F);
        const float pcx = d0*w + cx, pcy = d1*h + cy;
        const float pw = expf(dw)*w, ph = expf(dh)*h;

        const int n = p*9 + a;
        g_props[n*4+0] = pcx - 0.5f*pw;
        g_props[n*4+1] = pcy - 0.5f*ph;
        g_props[n*4+2] = pcx + 0.5f*pw;
        g_props[n*4+3] = pcy + 0.5f*ph;
        g_scores[n] = 1.0f / (1.0f + expf(-cls));
    }
}

// ---------------- K3: exact top-6000 via 4-pass radix select ----------------
__global__ void topk_init()
{
    int i = blockIdx.x*blockDim.x + threadIdx.x;
    if (i < SORT_N) g_sel[i] = ~0ull;
    if (i < 256) g_hist[i] = 0u;
    if (i == 0) { g_state[0] = 0u; g_state[1] = PRE_K; g_selcnt = 0u; }
}

__global__ __launch_bounds__(256) void topk_hist(int pass, int shift)
{
    __shared__ unsigned int sh[256];
    const int tid = threadIdx.x;
    sh[tid] = 0u;
    __syncthreads();
    int i = blockIdx.x*256 + tid;
    if (i < NANCH) {
        unsigned int key = __float_as_uint(g_scores[i]);
        bool ok = (pass == 0) || ((key >> (shift+8)) == g_state[0]);
        if (ok) atomicAdd(&sh[(key >> shift) & 255], 1u);
    }
    __syncthreads();
    if (sh[tid]) atomicAdd(&g_hist[tid], sh[tid]);
}

__global__ void topk_select()
{
    if (threadIdx.x == 0) {
        unsigned int kneed = g_state[1];
        unsigned int cum = 0; int chosen = 0;
        for (int d = 255; d >= 0; d--) {
            unsigned int c = g_hist[d];
            if (cum + c >= kneed) { chosen = d; break; }
            cum += c;
        }
        g_state[0] = (g_state[0] << 8) | (unsigned int)chosen;
        g_state[1] = kneed - cum;
    }
    __syncthreads();
    g_hist[threadIdx.x] = 0u;     // 256 threads
}

__global__ __launch_bounds__(256) void topk_compact()
{
    int i = blockIdx.x*256 + threadIdx.x;
    if (i >= NANCH) return;
    unsigned int key = __float_as_uint(g_scores[i]);
    unsigned int T = g_state[0];
    if (key >= T) {
        unsigned int pos = atomicAdd(&g_selcnt, 1u);
        if (pos < SORT_N)
            g_sel[pos] = ((unsigned long long)(~key) << 32) | (unsigned int)i;
    }
}

// sort 8192 64-bit keys ascending ((~scorebits)<<32 | idx) -> score desc, idx asc
__global__ __launch_bounds__(1024) void topk_sort()
{
    extern __shared__ unsigned long long S[];
    const int tid = threadIdx.x;
    for (int k = tid; k < SORT_N; k += 1024) S[k] = g_sel[k];
    __syncthreads();
    for (int k = 2; k <= SORT_N; k <<= 1) {
        for (int j = k >> 1; j > 0; j >>= 1) {
            for (int t = tid; t < SORT_N; t += 1024) {
                int ixj = t ^ j;
                if (ixj > t) {
                    unsigned long long a = S[t], b = S[ixj];
                    bool up = (t & k) == 0;
                    if ((a > b) == up) { S[t] = b; S[ixj] = a; }
                }
            }
            __syncthreads();
        }
    }
    for (int k = tid; k < PRE_K; k += 1024) g_sel[k] = S[k];
}

// ---------------- K4: gather + clip + min-size validity ----------------
__global__ __launch_bounds__(256) void prep_kernel()
{
    int i = blockIdx.x*256 + threadIdx.x;
    if (i >= PRE_K) return;
    unsigned long long sel = g_sel[i];
    unsigned int idx = (unsigned int)(sel & 0xffffffffull);
    unsigned int kb = ~(unsigned int)(sel >> 32);
    float scv = __uint_as_float(kb);
    float x1 = g_props[idx*4+0], y1 = g_props[idx*4+1];
    float x2 = g_props[idx*4+2], y2 = g_props[idx*4+3];
    x1 = fminf(fmaxf(x1, 0.f), IMSZ);
    y1 = fminf(fmaxf(y1, 0.f), IMSZ);
    x2 = fminf(fmaxf(x2, 0.f), IMSZ);
    y2 = fminf(fmaxf(y2, 0.f), IMSZ);
    g_b6[i*4+0] = x1; g_b6[i*4+1] = y1; g_b6[i*4+2] = x2; g_b6[i*4+3] = y2;
    g_s6[i] = scv;
    g_valid[i] = ((x2 - x1) >= 16.f && (y2 - y1) >= 16.f) ? 1 : 0;
}

// ---------------- K5: NMS suppression bitmask ----------------
// grid(94 rowblocks, 94 colblocks), 64 threads: thread = row i, word = colblock
__global__ __launch_bounds__(64) void nms_mask_kernel()
{
    const int rb = blockIdx.x, cb = blockIdx.y;
    const int tid = threadIdx.x;
    __shared__ float cbx1[64], cby1[64], cbx2[64], cby2[64];
    const int j0 = cb*64;
    {
        int j = j0 + tid;
        float a=0,b=0,c=0,d=0;
        if (j < PRE_K) { a=g_b6[j*4+0]; b=g_b6[j*4+1]; c=g_b6[j*4+2]; d=g_b6[j*4+3]; }
        cbx1[tid]=a; cby1[tid]=b; cbx2[tid]=c; cby2[tid]=d;
    }
    __syncthreads();
    const int i = rb*64 + tid;
    if (i >= PRE_K) return;
    if (cb < rb) { g_mask[i*NWORDS + cb] = 0ull; return; }

    const float ix1 = g_b6[i*4+0], iy1 = g_b6[i*4+1];
    const float ix2 = g_b6[i*4+2], iy2 = g_b6[i*4+3];
    const float ai = (ix2-ix1)*(iy2-iy1);
    unsigned long long bits = 0ull;
#pragma unroll 4
    for (int jj = 0; jj < 64; jj++) {
        const int j = j0 + jj;
        if (j <= i || j >= PRE_K) continue;
        float xx1 = fmaxf(ix1, cbx1[jj]);
        float yy1 = fmaxf(iy1, cby1[jj]);
        float xx2 = fminf(ix2, cbx2[jj]);
        float yy2 = fminf(iy2, cby2[jj]);
        float inter = fmaxf(xx2-xx1, 0.f) * fmaxf(yy2-yy1, 0.f);
        float aj = (cbx2[jj]-cbx1[jj])*(cby2[jj]-cby1[jj]);
        float iou = inter / (ai + aj - inter);
        if (iou > 0.7f) bits |= (1ull << jj);
    }
    g_mask[i*NWORDS + cb] = bits;
}

// ---------------- K6: greedy serial scan (1 warp, depth-16 row prefetch) ----------------
#define PF 16
__global__ __launch_bounds__(32) void nms_scan_kernel()
{
    const int l = threadIdx.x;
    unsigned long long rem0 = 0ull, rem1 = 0ull, rem2 = 0ull;

    // initialize removal bits from invalid boxes
#pragma unroll
    for (int s = 0; s < 3; s++) {
        int w = l + 32*s;
        unsigned long long v = 0ull;
        if (w < NWORDS) {
            for (int b = 0; b < 64; b++) {
                int i = w*64 + b;
                if (i < PRE_K && g_valid[i] == 0) v |= (1ull << b);
            }
        }
        if (s == 0) rem0 = v; else if (s == 1) rem1 = v; else rem2 = v;
    }

    unsigned long long pa[PF], pb[PF], pc[PF];
#pragma unroll
    for (int b = 0; b < PF; b++) {
        const unsigned long long* row = g_mask + (size_t)b*NWORDS;
        pa[b] = row[l];
        pb[b] = (l + 32 < NWORDS) ? row[l+32] : 0ull;
        pc[b] = (l < NWORDS - 64) ? row[l+64] : 0ull;
    }

    for (int i0 = 0; i0 < PRE_K; i0 += PF) {
#pragma unroll
        for (int u = 0; u < PF; u++) {
            const int i = i0 + u;
            const int w = i >> 6;
            const int src = w & 31;
            const int slot = w >> 5;
            unsigned long long myword = (slot == 0) ? rem0 : ((slot == 1) ? rem1 : rem2);
            unsigned long long word = __shfl_sync(0xffffffffu, myword, src);
            const bool sup = (word >> (i & 63)) & 1ull;
            if (!sup) { rem0 |= pa[u]; rem1 |= pb[u]; rem2 |= pc[u]; }
            if (l == 0) g_keep[i] = sup ? 0 : 1;
            const int nx = i + PF;
            if (nx < PRE_K) {
                const unsigned long long* row = g_mask + (size_t)nx*NWORDS;
                pa[u] = row[l];
                pb[u] = (l + 32 < NWORDS) ? row[l+32] : 0ull;
                pc[u] = (l < NWORDS - 64) ? row[l+64] : 0ull;
            }
        }
    }
}

// ---------------- K7: compact first 300 kept (already score-sorted) ----------------
__global__ __launch_bounds__(256) void out_kernel(float* __restrict__ out)
{
    const int tid = threadIdx.x;
    for (int k = tid; k < POST_K*5; k += 256) out[k] = 0.f;
    __shared__ int cnts[256];
    __shared__ int offs[256];
    int c = 0;
    if (tid < 250) {
        for (int j = 0; j < 24; j++) c += g_keep[tid*24 + j];
    }
    cnts[tid] = c;
    __syncthreads();
    if (tid == 0) {
        int s = 0;
        for (int t = 0; t < 250; t++) { offs[t] = s; s += cnts[t]; }
    }
    __syncthreads();
    if (tid < 250) {
        int r = offs[tid];
        for (int j = 0; j < 24; j++) {
            int i = tid*24 + j;
            if (g_keep[i]) {
                if (r < POST_K) {
                    out[r*5+0] = g_b6[i*4+0];
                    out[r*5+1] = g_b6[i*4+1];
                    out[r*5+2] = g_b6[i*4+2];
                    out[r*5+3] = g_b6[i*4+3];
                    out[r*5+4] = g_s6[i];
                }
                r++;
            }
        }
    }
}

// ---------------- launch ----------------
extern "C" void kernel_launch(void* const* d_in, const int* in_sizes, int n_in,
                              void* d_out, int out_size)
{
    (void)in_sizes; (void)n_in; (void)out_size;
    const float* feat = (const float*)d_in[1];
    const float* cw   = (const float*)d_in[2];
    const float* cb   = (const float*)d_in[3];
    const float* clsw = (const float*)d_in[4];
    const float* clsb = (const float*)d_in[5];
    const float* bw   = (const float*)d_in[6];
    const float* bb   = (const float*)d_in[7];
    float* out = (float*)d_out;

    conv3_kernel<<<dim3(256, 4), 128>>>(feat, cw, cb);
    head_kernel<<<256, 256>>>(clsw, clsb, bw, bb);

    topk_init<<<32, 256>>>();
    topk_hist<<<576, 256>>>(0, 24); topk_select<<<1, 256>>>();
    topk_hist<<<576, 256>>>(1, 16); topk_select<<<1, 256>>>();
    topk_hist<<<576, 256>>>(2, 8);  topk_select<<<1, 256>>>();
    topk_hist<<<576, 256>>>(3, 0);  topk_select<<<1, 256>>>();
    topk_compact<<<576, 256>>>();

    cudaFuncSetAttribute(topk_sort, cudaFuncAttributeMaxDynamicSharedMemorySize, 65536);
    topk_sort<<<1, 1024, 65536>>>();

    prep_kernel<<<24, 256>>>();
    nms_mask_kernel<<<dim3(94, 94), 64>>>();
    nms_scan_kernel<<<1, 32>>>();
    out_kernel<<<1, 256>>>(out);
}

// round 9
// speedup vs baseline: 1.5095x; 1.3687x over previous
#include <cuda_runtime.h>
#include <cstdint>

// ---------------- problem constants ----------------
#define HH 128
#define WW 128
#define CIN 256
#define NPIX (HH*WW)            // 16384
#define NA 9
#define NANCH (NPIX*NA)         // 147456
#define PRE_K 6000
#define POST_K 300
#define NWORDS 94               // ceil(6000/64)
#define SORT_N 8192
#define DW_CLIP_F 4.135166556742356f
#define IMSZ 1024.0f

// packed fp32x2 helpers (sm_100+): bit-identical IEEE fp32 RN, 2x fma throughput
#define FMA2(d,a,b) asm("fma.rn.f32x2 %0, %1, %2, %0;" : "+l"(d) : "l"(a), "l"(b))
#define PACK2(d,s)  asm("mov.b64 %0, {%1, %1};" : "=l"(d) : "f"(s))
#define UNPACK2(lo,hi,v) asm("mov.b64 {%0, %1}, %2;" : "=f"(lo), "=f"(hi) : "l"(v))

// ---------------- device scratch ----------------
__device__ float g_rpnfeat[CIN*NPIX];                 // 16.8 MB
__device__ float g_scores[NANCH];
__device__ float g_props[NANCH*4];
__device__ unsigned int g_hist16[65536];
__device__ unsigned int g_state[2];                   // [0]=prefix, [1]=kneed
__device__ unsigned int g_selcnt;
__device__ unsigned long long g_sel[SORT_N];
__device__ float g_b6[PRE_K*4];
__device__ float g_s6[PRE_K];
__device__ unsigned char g_valid[PRE_K];
__device__ unsigned long long g_mask[PRE_K*NWORDS];   // 4.5 MB (upper triangle valid)

// ---------------- K1: 3x3 conv + bias + relu (implicit GEMM, f32x2) ----------------
__global__ __launch_bounds__(128) void conv3_kernel(const float* __restrict__ feat,
                                                    const float* __restrict__ wt,
                                                    const float* __restrict__ bias)
{
    __shared__ __align__(16) float As[8*3*68];
    __shared__ __align__(16) float Ws[72*64];

    const int tid = threadIdx.x;
    const int tx  = tid & 15;
    const int ty  = tid >> 4;
    const int px4 = tx * 4;
    const int co8 = ty * 8;
    const int bx = blockIdx.x;
    const int y  = bx >> 1;
    const int x0 = (bx & 1) * 64;
    const int co0 = blockIdx.y * 64;

    unsigned long long acc[16];
#pragma unroll
    for (int i = 0; i < 16; i++) acc[i] = 0ull;

    for (int ci0 = 0; ci0 < CIN; ci0 += 8) {
        __syncthreads();
        for (int e = tid; e < 8*3*66; e += 128) {
            int ci = e / (3*66);
            int rr = e % (3*66);
            int r  = rr / 66;
            int xi = rr % 66;
            int yy = y + r - 1;
            int xx = x0 + xi - 1;
            float v = 0.f;
            if (yy >= 0 && yy < HH && xx >= 0 && xx < WW)
                v = feat[(ci0+ci)*NPIX + yy*WW + xx];
            As[(ci*3+r)*68 + xi] = v;
        }
        {
            int co_l = tid >> 1, sub = tid & 1;
            const float* wsrc = wt + ((size_t)(co0+co_l)*CIN + ci0)*9 + sub*36;
#pragma unroll
            for (int q = 0; q < 36; q++)
                Ws[(sub*36 + q)*64 + co_l] = wsrc[q];
        }
        __syncthreads();

#pragma unroll
        for (int ci = 0; ci < 8; ci++) {
#pragma unroll
            for (int ky = 0; ky < 3; ky++) {
                const int rowb = (ci*3+ky)*68 + px4;
                const float4 blo = *(const float4*)&As[rowb];
                const float4 bhi = *(const float4*)&As[rowb + 4];
                unsigned long long pb[6];
                PACK2(pb[0], blo.x); PACK2(pb[1], blo.y); PACK2(pb[2], blo.z);
                PACK2(pb[3], blo.w); PACK2(pb[4], bhi.x); PACK2(pb[5], bhi.y);
#pragma unroll
                for (int kx = 0; kx < 3; kx++) {
                    const ulonglong2* wp =
                        (const ulonglong2*)&Ws[(ci*9 + ky*3 + kx)*64 + co8];
                    const ulonglong2 w0 = wp[0];
                    const ulonglong2 w1 = wp[1];
#pragma unroll
                    for (int c = 0; c < 4; c++) {
                        FMA2(acc[0*4+c], w0.x, pb[kx+c]);
                        FMA2(acc[1*4+c], w0.y, pb[kx+c]);
                        FMA2(acc[2*4+c], w1.x, pb[kx+c]);
                        FMA2(acc[3*4+c], w1.y, pb[kx+c]);
                    }
                }
            }
        }
    }

#pragma unroll
    for (int rp = 0; rp < 4; rp++) {
        const int coA = co0 + co8 + rp*2;
        const int coB = coA + 1;
        const float bA = bias[coA];
        const float bB = bias[coB];
#pragma unroll
        for (int c = 0; c < 4; c++) {
            float lo, hi;
            UNPACK2(lo, hi, acc[rp*4+c]);
            const int p = y*WW + x0 + px4 + c;
            g_rpnfeat[coA*NPIX + p] = fmaxf(lo + bA, 0.f);
            g_rpnfeat[coB*NPIX + p] = fmaxf(hi + bB, 0.f);
        }
    }
}

// ---------------- K2: 1x1 heads (45 ch) + anchor decode + sigmoid ----------------
__global__ __launch_bounds__(256) void head_kernel(const float* __restrict__ clsw,
                                                   const float* __restrict__ clsb,
                                                   const float* __restrict__ boxw,
                                                   const float* __restrict__ boxb)
{
    __shared__ float Ft[32*64];
    __shared__ float Wc[32*48];
    __shared__ float st[64*48];

    const int tid = threadIdx.x;
    const int p0 = blockIdx.x * 64;
    const int px = tid & 63, g = tid >> 6;

    float acc[12];
#pragma unroll
    for (int j=0;j<12;j++) acc[j]=0.f;

    for (int c0 = 0; c0 < CIN; c0 += 32) {
        __syncthreads();
        for (int e = tid; e < 32*64; e += 256) {
            int ci = e >> 6, pp = e & 63;
            Ft[e] = g_rpnfeat[(c0+ci)*NPIX + p0 + pp];
        }
        for (int e = tid; e < 32*45; e += 256) {
            int ci = e / 45, ch = e % 45;
            float v = (ch < 9) ? clsw[ch*CIN + c0 + ci] : boxw[(ch-9)*CIN + c0 + ci];
            Wc[ci*48 + ch] = v;
        }
        __syncthreads();
#pragma unroll 8
        for (int ci = 0; ci < 32; ci++) {
            float f = Ft[ci*64 + px];
#pragma unroll
            for (int j = 0; j < 12; j++)
                acc[j] += Wc[ci*48 + g*12 + j] * f;
        }
    }
    __syncthreads();
#pragma unroll
    for (int j = 0; j < 12; j++) {
        int ch = g*12 + j;
        if (ch < 45) st[px*48 + ch] = acc[j];
    }
    __syncthreads();

    for (int t2 = tid; t2 < 64*9; t2 += 256) {
        const int a = t2 % 9, pp = t2 / 9;
        const int p = p0 + pp;
        const int yy = p >> 7, xx = p & 127;

        float cls = st[pp*48 + a] + clsb[a];
        float d0 = st[pp*48 + 9 + a*4 + 0] + boxb[a*4+0];
        float d1 = st[pp*48 + 9 + a*4 + 1] + boxb[a*4+1];
        float d2 = st[pp*48 + 9 + a*4 + 2] + boxb[a*4+2];
        float d3 = st[pp*48 + 9 + a*4 + 3] + boxb[a*4+3];

        const int iar = a / 3, jsc = a % 3;
        const float ar = (iar==0) ? 0.5f : (iar==1 ? 1.0f : 2.0f);
        const float sc = (jsc==0) ? 128.f : (jsc==1 ? 256.f : 512.f);
        const float hr = sqrtf(ar);
        const float wr = 1.0f / hr;
        const float hs = hr * sc, ws = wr * sc;
        const float bx1 = rintf(-ws*0.5f), by1 = rintf(-hs*0.5f);
        const float bx2 = rintf( ws*0.5f), by2 = rintf( hs*0.5f);
        const float ax1 = xx*8.0f + bx1, ay1 = yy*8.0f + by1;
        const float ax2 = xx*8.0f + bx2, ay2 = yy*8.0f + by2;

        const float w  = ax2 - ax1, h = ay2 - ay1;
        const float cx = ax1 + 0.5f*w, cy = ay1 + 0.5f*h;
        const float dw = fminf(d2, DW_CLIP_F);
        const float dh = fminf(d3, DW_CLIP_F);
        const float pcx = d0*w + cx, pcy = d1*h + cy;
        const float pw = expf(dw)*w, ph = expf(dh)*h;

        const int n = p*9 + a;
        g_props[n*4+0] = pcx - 0.5f*pw;
        g_props[n*4+1] = pcy - 0.5f*ph;
        g_props[n*4+2] = pcx + 0.5f*pw;
        g_props[n*4+3] = pcy + 0.5f*ph;
        g_scores[n] = 1.0f / (1.0f + expf(-cls));
    }
}

// ---------------- K3: exact top-6000 via 2x16-bit radix select ----------------
__global__ __launch_bounds__(1024) void topk_init()
{
    int i = blockIdx.x*1024 + threadIdx.x;      // 64 blocks -> 65536 exactly
    g_hist16[i] = 0u;
    if (i < SORT_N) g_sel[i] = ~0ull;
    if (i == 0) { g_state[0] = 0u; g_state[1] = PRE_K; g_selcnt = 0u; }
}

__global__ __launch_bounds__(256) void hist16_kernel(int pass)
{
    const int i = blockIdx.x*256 + threadIdx.x;   // 576*256 == NANCH exactly
    unsigned int key = __float_as_uint(g_scores[i]);
    unsigned int digit;
    bool ok;
    if (pass == 0) { digit = key >> 16; ok = true; }
    else { digit = key & 0xffffu; ok = ((key >> 16) == g_state[0]); }
    unsigned int v = ok ? digit : 0xffffffffu;
    unsigned int grp = __match_any_sync(0xffffffffu, v);
    int lane = threadIdx.x & 31;
    if (ok && lane == (__ffs(grp) - 1))
        atomicAdd(&g_hist16[digit], __popc(grp));
}

__global__ __launch_bounds__(1024) void sel16_kernel()
{
    __shared__ unsigned int s[1024];
    const int t = threadIdx.x;
    unsigned int part = 0;
#pragma unroll 8
    for (int b = 0; b < 64; b++) part += g_hist16[t*64 + b];
    s[t] = part;
    __syncthreads();
    for (int off = 1; off < 1024; off <<= 1) {
        unsigned int v = (t + off < 1024) ? s[t + off] : 0u;
        __syncthreads();
        s[t] += v;
        __syncthreads();
    }
    const unsigned int kneed = g_state[1];
    bool mine = (s[t] >= kneed) && (t == 1023 || s[t+1] < kneed);
    if (mine) {
        unsigned int cum = (t == 1023) ? 0u : s[t+1];
        const int base = t*64;
        unsigned int digit = (unsigned)base, nk = kneed;
        for (int b = 63; b >= 0; b--) {
            unsigned int c = g_hist16[base + b];
            if (cum + c >= kneed) { digit = base + b; nk = kneed - cum; break; }
            cum += c;
        }
        g_state[0] = (g_state[0] << 16) | digit;
        g_state[1] = nk;
    }
    __syncthreads();
    // zero hist for next pass
    for (int idx = t; idx < 65536; idx += 1024) g_hist16[idx] = 0u;
}

__global__ __launch_bounds__(256) void topk_compact()
{
    const int i = blockIdx.x*256 + threadIdx.x;
    unsigned int key = __float_as_uint(g_scores[i]);
    unsigned int T = g_state[0];
    if (key >= T) {
        unsigned int pos = atomicAdd(&g_selcnt, 1u);
        if (pos < SORT_N)
            g_sel[pos] = ((unsigned long long)(~key) << 32) | (unsigned int)i;
    }
}

// ---------------- K4: hierarchical bitonic sort (regs/shfl/smem) + fused prep ----
__global__ __launch_bounds__(1024) void topk_sort()
{
    extern __shared__ unsigned long long S[];
    const int t = threadIdx.x;
    unsigned long long r[8];
#pragma unroll
    for (int e = 0; e < 8; e++) r[e] = g_sel[t*8 + e];

    for (unsigned int k = 2; k <= SORT_N; k <<= 1) {
        // smem steps: j >= 256 (cross-warp)
        for (unsigned int j = k >> 1; j >= 256; j >>= 1) {
#pragma unroll
            for (int e = 0; e < 8; e++) S[t*8 + e] = r[e];
            __syncthreads();
#pragma unroll
            for (int e = 0; e < 8; e++) {
                const int i = t*8 + e;
                const unsigned long long p = S[i ^ j];
                const bool up = ((i & k) == 0);
                const bool lower = ((i & j) == 0);
                const unsigned long long mn = r[e] < p ? r[e] : p;
                const unsigned long long mx = r[e] < p ? p : r[e];
                r[e] = (up == lower) ? mn : mx;
            }
            __syncthreads();
        }
        // shfl steps: 8 <= j <= 128 (within warp)
        for (unsigned int j = ((k>>1) < 128u ? (k>>1) : 128u); j >= 8; j >>= 1) {
            const int ls = (int)(j >> 3);
            const bool lowthread = ((t & ls) == 0);
#pragma unroll
            for (int e = 0; e < 8; e++) {
                const unsigned long long p = __shfl_xor_sync(0xffffffffu, r[e], ls);
                const int i = t*8 + e;
                const bool up = ((i & k) == 0);
                const unsigned long long mn = r[e] < p ? r[e] : p;
                const unsigned long long mx = r[e] < p ? p : r[e];
                r[e] = (up == lowthread) ? mn : mx;
            }
        }
        // register steps: j <= 4 (intra-thread)
        for (unsigned int j = ((k>>1) < 4u ? (k>>1) : 4u); j >= 1; j >>= 1) {
#pragma unroll
            for (int e = 0; e < 8; e++) {
                if ((e & (int)j) == 0) {
                    const int i = t*8 + e;
                    const bool up = ((i & k) == 0);
                    const unsigned long long a = r[e], b = r[e | (int)j];
                    if ((a > b) == up) { r[e] = b; r[e | (int)j] = a; }
                }
            }
        }
    }

    // fused prep: clip + min-size validity on the sorted top-6000
#pragma unroll
    for (int e = 0; e < 8; e++) {
        const int p = t*8 + e;
        if (p < PRE_K) {
            const unsigned long long sel = r[e];
            const unsigned int idx = (unsigned int)(sel & 0xffffffffull);
            const unsigned int kb = ~(unsigned int)(sel >> 32);
            float x1 = g_props[idx*4+0], y1 = g_props[idx*4+1];
            float x2 = g_props[idx*4+2], y2 = g_props[idx*4+3];
            x1 = fminf(fmaxf(x1, 0.f), IMSZ);
            y1 = fminf(fmaxf(y1, 0.f), IMSZ);
            x2 = fminf(fmaxf(x2, 0.f), IMSZ);
            y2 = fminf(fmaxf(y2, 0.f), IMSZ);
            g_b6[p*4+0] = x1; g_b6[p*4+1] = y1; g_b6[p*4+2] = x2; g_b6[p*4+3] = y2;
            g_s6[p] = __uint_as_float(kb);
            g_valid[p] = ((x2 - x1) >= 16.f && (y2 - y1) >= 16.f) ? 1 : 0;
        }
    }
}

// ---------------- K5: NMS suppression bitmask (upper triangle only) ----------------
__global__ __launch_bounds__(64) void nms_mask_kernel()
{
    const int rb = blockIdx.x, cb = blockIdx.y;
    if (cb < rb) return;                  // lower triangle never read (masked in scan)
    const int tid = threadIdx.x;
    __shared__ float cbx1[64], cby1[64], cbx2[64], cby2[64];
    const int j0 = cb*64;
    {
        int j = j0 + tid;
        float a=0,b=0,c=0,d=0;
        if (j < PRE_K) { a=g_b6[j*4+0]; b=g_b6[j*4+1]; c=g_b6[j*4+2]; d=g_b6[j*4+3]; }
        cbx1[tid]=a; cby1[tid]=b; cbx2[tid]=c; cby2[tid]=d;
    }
    __syncthreads();
    const int i = rb*64 + tid;
    if (i >= PRE_K) return;

    const float ix1 = g_b6[i*4+0], iy1 = g_b6[i*4+1];
    const float ix2 = g_b6[i*4+2], iy2 = g_b6[i*4+3];
    const float ai = (ix2-ix1)*(iy2-iy1);
    unsigned long long bits = 0ull;
#pragma unroll 4
    for (int jj = 0; jj < 64; jj++) {
        const int j = j0 + jj;
        if (j <= i || j >= PRE_K) continue;
        float xx1 = fmaxf(ix1, cbx1[jj]);
        float yy1 = fmaxf(iy1, cby1[jj]);
        float xx2 = fminf(ix2, cbx2[jj]);
        float yy2 = fminf(iy2, cby2[jj]);
        float inter = fmaxf(xx2-xx1, 0.f) * fmaxf(yy2-yy1, 0.f);
        float aj = (cbx2[jj]-cbx1[jj])*(cby2[jj]-cby1[jj]);
        float iou = inter / (ai + aj - inter);
        if (iou > 0.7f) bits |= (1ull << jj);
    }
    g_mask[(size_t)i*NWORDS + cb] = bits;
}

// ---------------- K6: greedy serial scan, early-exit @300 keeps, direct output ----
#define PF 16
__global__ __launch_bounds__(32) void nms_scan_out(float* __restrict__ out)
{
    const int l = threadIdx.x;
    __shared__ int list[POST_K];

    // zero the whole output (rows past kept count must be 0)
    for (int k = l; k < POST_K*5; k += 32) out[k] = 0.f;

    unsigned long long rem0 = 0ull, rem1 = 0ull, rem2 = 0ull;
#pragma unroll
    for (int s = 0; s < 3; s++) {
        int w = l + 32*s;
        unsigned long long v = 0ull;
        if (w < NWORDS) {
            int base = w*64;
            int lim = (PRE_K - base) < 64 ? (PRE_K - base) : 64;
            for (int b = 0; b < lim; b++)
                if (!g_valid[base + b]) v |= (1ull << b);
        }
        if (s == 0) rem0 = v; else if (s == 1) rem1 = v; else rem2 = v;
    }

    unsigned long long pa[PF], pb[PF], pc[PF];
#pragma unroll
    for (int u = 0; u < PF; u++) {
        const unsigned long long* row = g_mask + (size_t)u*NWORDS;
        // rows 0..15 -> word0 = 0, so l >= w0 always for pa
        pa[u] = row[l];
        pb[u] = (l + 32 < NWORDS) ? row[l+32] : 0ull;
        pc[u] = (l + 64 < NWORDS) ? row[l+64] : 0ull;
    }

    int kept = 0;
    for (int i0 = 0; i0 < PRE_K; i0 += PF) {
#pragma unroll
        for (int u = 0; u < PF; u++) {
            const int i = i0 + u;
            const int w = i >> 6;
            const int src = w & 31;
            const int slot = w >> 5;
            unsigned long long my = (slot == 0) ? rem0 : ((slot == 1) ? rem1 : rem2);
            unsigned long long word = __shfl_sync(0xffffffffu, my, src);
            const bool sup = (word >> (i & 63)) & 1ull;
            if (!sup) {
                rem0 |= pa[u]; rem1 |= pb[u]; rem2 |= pc[u];
                if (l == 0) list[kept] = i;
                kept++;
                if (kept == POST_K) goto done;
            }
            const int nx = i + PF;
            if (nx < PRE_K) {
                const unsigned long long* row = g_mask + (size_t)nx*NWORDS;
                const int w0 = nx >> 6;
                pa[u] = (l >= w0) ? row[l] : 0ull;
                pb[u] = (l+32 >= w0 && l+32 < NWORDS) ? row[l+32] : 0ull;
                pc[u] = (l+64 >= w0 && l+64 < NWORDS) ? row[l+64] : 0ull;
            }
        }
    }
done:
    __syncwarp();
    for (int rI = l; rI < kept; rI += 32) {
        const int i = list[rI];
        out[rI*5+0] = g_b6[i*4+0];
        out[rI*5+1] = g_b6[i*4+1];
        out[rI*5+2] = g_b6[i*4+2];
        out[rI*5+3] = g_b6[i*4+3];
        out[rI*5+4] = g_s6[i];
    }
}

// ---------------- launch ----------------
extern "C" void kernel_launch(void* const* d_in, const int* in_sizes, int n_in,
                              void* d_out, int out_size)
{
    (void)in_sizes; (void)n_in; (void)out_size;
    const float* feat = (const float*)d_in[1];
    const float* cw   = (const float*)d_in[2];
    const float* cb   = (const float*)d_in[3];
    const float* clsw = (const float*)d_in[4];
    const float* clsb = (const float*)d_in[5];
    const float* bw   = (const float*)d_in[6];
    const float* bb   = (const float*)d_in[7];
    float* out = (float*)d_out;

    conv3_kernel<<<dim3(256, 4), 128>>>(feat, cw, cb);
    head_kernel<<<256, 256>>>(clsw, clsb, bw, bb);

    topk_init<<<64, 1024>>>();
    hist16_kernel<<<576, 256>>>(0);
    sel16_kernel<<<1, 1024>>>();
    hist16_kernel<<<576, 256>>>(1);
    sel16_kernel<<<1, 1024>>>();
    topk_compact<<<576, 256>>>();

    cudaFuncSetAttribute(topk_sort, cudaFuncAttributeMaxDynamicSharedMemorySize, 65536);
    topk_sort<<<1, 1024, 65536>>>();

    nms_mask_kernel<<<dim3(94, 94), 64>>>();
    nms_scan_out<<<1, 32>>>(out);
}

// round 10
// speedup vs baseline: 1.8129x; 1.2010x over previous
#include <cuda_runtime.h>
#include <cstdint>

// ---------------- problem constants ----------------
#define HH 128
#define WW 128
#define CIN 256
#define NPIX (HH*WW)            // 16384
#define NA 9
#define NANCH (NPIX*NA)         // 147456
#define PRE_K 6000
#define POST_K 300
#define NWORDS 94               // ceil(6000/64)
#define SORT_N 8192
#define DW_CLIP_F 4.135166556742356f
#define IMSZ 1024.0f

// packed fp32x2 helpers (sm_100+): bit-identical IEEE fp32 RN
#define FMA2(d,a,b) asm("fma.rn.f32x2 %0, %1, %2, %0;" : "+l"(d) : "l"(a), "l"(b))
#define PACK2(d,s)  asm("mov.b64 %0, {%1, %1};" : "=l"(d) : "f"(s))
#define UNPACK2(lo,hi,v) asm("mov.b64 {%0, %1}, %2;" : "=f"(lo), "=f"(hi) : "l"(v))

// ---------------- device scratch ----------------
__device__ float g_rpnfeat[CIN*NPIX];                 // 16.8 MB
__device__ float g_scores[NANCH];
__device__ float g_props[NANCH*4];
__device__ unsigned int g_hist16[65536];
__device__ unsigned int g_state[2];                   // [0]=prefix, [1]=kneed
__device__ unsigned int g_selcnt;
__device__ unsigned long long g_sel[SORT_N];
__device__ float g_b6[PRE_K*4];
__device__ float g_s6[PRE_K];
__device__ unsigned char g_valid[PRE_K];
__device__ unsigned long long g_mask[PRE_K*NWORDS];   // 4.5 MB (upper triangle valid)

// ---------------- init split into 5 launches (so conv3 is launch #6 for ncu -s 5) --
__global__ __launch_bounds__(1024) void init_hist(int q)
{
    g_hist16[q*16384 + blockIdx.x*1024 + threadIdx.x] = 0u;
}
__global__ __launch_bounds__(1024) void init_sel()
{
    const int i = blockIdx.x*1024 + threadIdx.x;   // 8 blocks -> 8192 exactly
    g_sel[i] = ~0ull;
    if (i == 0) { g_state[0] = 0u; g_state[1] = PRE_K; g_selcnt = 0u; }
}

// ---------------- K1: 3x3 conv + bias + relu (implicit GEMM, f32x2) ----------------
// block = 128 threads. tile = 64 co x 64 px (one y row, half x).
// thread tile = 8 co x 4 px, accumulated as 16 f32x2 pairs (pair dim = co).
__global__ __launch_bounds__(128) void conv3_kernel(const float* __restrict__ feat,
                                                    const float* __restrict__ wt,
                                                    const float* __restrict__ bias)
{
    __shared__ __align__(16) float As[24*68];    // [ci*3+r][xi 0..65], pad 68
    __shared__ __align__(16) float Ws[72*64];    // [(ci*9+tap)][co_local]

    const int tid = threadIdx.x;
    const int lane = tid & 31;
    const int wid  = tid >> 5;
    const int tx  = tid & 15;
    const int ty  = tid >> 4;
    const int px4 = tx * 4;
    const int co8 = ty * 8;
    const int bx = blockIdx.x;
    const int y  = bx >> 1;
    const int x0 = (bx & 1) * 64;
    const int co0 = blockIdx.y * 64;

    // Ws fill pointers (invariant except +72 floats per ci0 step)
    const int co_l = tid >> 1, sub = tid & 1;
    const float* wsrc = wt + ((size_t)(co0+co_l)*CIN)*9 + sub*36;

    unsigned long long acc[16];
#pragma unroll
    for (int i = 0; i < 16; i++) acc[i] = 0ull;

    for (int ci0 = 0; ci0 < CIN; ci0 += 8) {
        __syncthreads();
        // ---- As fill: warp-row mapping, no div/mod on hot path ----
        {
            const float* fbase = feat + (size_t)ci0*NPIX;
            for (int row = wid; row < 24; row += 4) {
                const int ci = (row * 0x5556) >> 16;   // row/3 for row<24
                const int r  = row - ci*3;
                const int yy = y + r - 1;
                const bool yok = (yy >= 0) && (yy < HH);
                float* dst = &As[row*68];
                const float* src = fbase + ci*NPIX + yy*WW + (x0 - 1);
                // xi: lane, lane+32, lane+64 (<66)
                {
                    const int xi = lane;
                    const int xx = x0 + xi - 1;
                    dst[xi] = (yok && xx >= 0) ? src[xi] : 0.f;
                }
                {
                    const int xi = lane + 32;
                    dst[xi] = yok ? src[xi] : 0.f;     // interior columns always in range
                }
                if (lane < 2) {
                    const int xi = lane + 64;
                    const int xx = x0 + xi - 1;
                    dst[xi] = (yok && xx < WW) ? src[xi] : 0.f;
                }
            }
        }
        // ---- Ws fill: 9 x LDG.128, scatter STS ----
        {
            const float4* w4 = (const float4*)(wsrc + (size_t)ci0*9);
#pragma unroll
            for (int q4 = 0; q4 < 9; q4++) {
                const float4 v = w4[q4];
                const int kt = sub*36 + q4*4;
                Ws[(kt+0)*64 + co_l] = v.x;
                Ws[(kt+1)*64 + co_l] = v.y;
                Ws[(kt+2)*64 + co_l] = v.z;
                Ws[(kt+3)*64 + co_l] = v.w;
            }
        }
        __syncthreads();

#pragma unroll
        for (int ci = 0; ci < 8; ci++) {
#pragma unroll
            for (int ky = 0; ky < 3; ky++) {
                const int rowb = (ci*3+ky)*68 + px4;
                const float4 blo = *(const float4*)&As[rowb];
                const float4 bhi = *(const float4*)&As[rowb + 4];
                unsigned long long pb[6];
                PACK2(pb[0], blo.x); PACK2(pb[1], blo.y); PACK2(pb[2], blo.z);
                PACK2(pb[3], blo.w); PACK2(pb[4], bhi.x); PACK2(pb[5], bhi.y);
#pragma unroll
                for (int kx = 0; kx < 3; kx++) {
                    const ulonglong2* wp =
                        (const ulonglong2*)&Ws[(ci*9 + ky*3 + kx)*64 + co8];
                    const ulonglong2 w0 = wp[0];
                    const ulonglong2 w1 = wp[1];
#pragma unroll
                    for (int c = 0; c < 4; c++) {
                        FMA2(acc[0*4+c], w0.x, pb[kx+c]);
                        FMA2(acc[1*4+c], w0.y, pb[kx+c]);
                        FMA2(acc[2*4+c], w1.x, pb[kx+c]);
                        FMA2(acc[3*4+c], w1.y, pb[kx+c]);
                    }
                }
            }
        }
    }

#pragma unroll
    for (int rp = 0; rp < 4; rp++) {
        const int coA = co0 + co8 + rp*2;
        const int coB = coA + 1;
        const float bA = bias[coA];
        const float bB = bias[coB];
#pragma unroll
        for (int c = 0; c < 4; c++) {
            float lo, hi;
            UNPACK2(lo, hi, acc[rp*4+c]);
            const int p = y*WW + x0 + px4 + c;
            g_rpnfeat[coA*NPIX + p] = fmaxf(lo + bA, 0.f);
            g_rpnfeat[coB*NPIX + p] = fmaxf(hi + bB, 0.f);
        }
    }
}

// ---------------- K2: 1x1 heads (45 ch) + anchor decode + sigmoid ----------------
__global__ __launch_bounds__(256) void head_kernel(const float* __restrict__ clsw,
                                                   const float* __restrict__ clsb,
                                                   const float* __restrict__ boxw,
                                                   const float* __restrict__ boxb)
{
    __shared__ float Ft[32*64];
    __shared__ float Wc[32*48];
    __shared__ float st[64*48];

    const int tid = threadIdx.x;
    const int p0 = blockIdx.x * 64;
    const int px = tid & 63, g = tid >> 6;

    float acc[12];
#pragma unroll
    for (int j=0;j<12;j++) acc[j]=0.f;

    for (int c0 = 0; c0 < CIN; c0 += 32) {
        __syncthreads();
        for (int e = tid; e < 32*64; e += 256) {
            int ci = e >> 6, pp = e & 63;
            Ft[e] = g_rpnfeat[(c0+ci)*NPIX + p0 + pp];
        }
        for (int e = tid; e < 32*45; e += 256) {
            int ci = e / 45, ch = e % 45;
            float v = (ch < 9) ? clsw[ch*CIN + c0 + ci] : boxw[(ch-9)*CIN + c0 + ci];
            Wc[ci*48 + ch] = v;
        }
        __syncthreads();
#pragma unroll 8
        for (int ci = 0; ci < 32; ci++) {
            float f = Ft[ci*64 + px];
#pragma unroll
            for (int j = 0; j < 12; j++)
                acc[j] += Wc[ci*48 + g*12 + j] * f;
        }
    }
    __syncthreads();
#pragma unroll
    for (int j = 0; j < 12; j++) {
        int ch = g*12 + j;
        if (ch < 45) st[px*48 + ch] = acc[j];
    }
    __syncthreads();

    for (int t2 = tid; t2 < 64*9; t2 += 256) {
        const int a = t2 % 9, pp = t2 / 9;
        const int p = p0 + pp;
        const int yy = p >> 7, xx = p & 127;

        float cls = st[pp*48 + a] + clsb[a];
        float d0 = st[pp*48 + 9 + a*4 + 0] + boxb[a*4+0];
        float d1 = st[pp*48 + 9 + a*4 + 1] + boxb[a*4+1];
        float d2 = st[pp*48 + 9 + a*4 + 2] + boxb[a*4+2];
        float d3 = st[pp*48 + 9 + a*4 + 3] + boxb[a*4+3];

        const int iar = a / 3, jsc = a % 3;
        const float ar = (iar==0) ? 0.5f : (iar==1 ? 1.0f : 2.0f);
        const float sc = (jsc==0) ? 128.f : (jsc==1 ? 256.f : 512.f);
        const float hr = sqrtf(ar);
        const float wr = 1.0f / hr;
        const float hs = hr * sc, ws = wr * sc;
        const float bx1 = rintf(-ws*0.5f), by1 = rintf(-hs*0.5f);
        const float bx2 = rintf( ws*0.5f), by2 = rintf( hs*0.5f);
        const float ax1 = xx*8.0f + bx1, ay1 = yy*8.0f + by1;
        const float ax2 = xx*8.0f + bx2, ay2 = yy*8.0f + by2;

        const float w  = ax2 - ax1, h = ay2 - ay1;
        const float cx = ax1 + 0.5f*w, cy = ay1 + 0.5f*h;
        const float dw = fminf(d2, DW_CLIP_F);
        const float dh = fminf(d3, DW_CLIP_F);
        const float pcx = d0*w + cx, pcy = d1*h + cy;
        const float pw = expf(dw)*w, ph = expf(dh)*h;

        const int n = p*9 + a;
        g_props[n*4+0] = pcx - 0.5f*pw;
        g_props[n*4+1] = pcy - 0.5f*ph;
        g_props[n*4+2] = pcx + 0.5f*pw;
        g_props[n*4+3] = pcy + 0.5f*ph;
        g_scores[n] = 1.0f / (1.0f + expf(-cls));
    }
}

// ---------------- K3: exact top-6000 via 2x16-bit radix select ----------------
__global__ __launch_bounds__(256) void hist16_kernel(int pass)
{
    const int i = blockIdx.x*256 + threadIdx.x;   // 576*256 == NANCH exactly
    unsigned int key = __float_as_uint(g_scores[i]);
    unsigned int digit;
    bool ok;
    if (pass == 0) { digit = key >> 16; ok = true; }
    else { digit = key & 0xffffu; ok = ((key >> 16) == g_state[0]); }
    unsigned int v = ok ? digit : 0xffffffffu;
    unsigned int grp = __match_any_sync(0xffffffffu, v);
    int lane = threadIdx.x & 31;
    if (ok && lane == (__ffs(grp) - 1))
        atomicAdd(&g_hist16[digit], __popc(grp));
}

__global__ __launch_bounds__(1024) void sel16_kernel(int zero_after)
{
    __shared__ unsigned int s[1024];
    const int t = threadIdx.x;
    unsigned int part = 0;
#pragma unroll 8
    for (int b = 0; b < 64; b++) part += g_hist16[t*64 + b];
    s[t] = part;
    __syncthreads();
    for (int off = 1; off < 1024; off <<= 1) {
        unsigned int v = (t + off < 1024) ? s[t + off] : 0u;
        __syncthreads();
        s[t] += v;
        __syncthreads();
    }
    const unsigned int kneed = g_state[1];
    bool mine = (s[t] >= kneed) && (t == 1023 || s[t+1] < kneed);
    if (mine) {
        unsigned int cum = (t == 1023) ? 0u : s[t+1];
        const int base = t*64;
        unsigned int digit = (unsigned)base, nk = kneed;
        for (int b = 63; b >= 0; b--) {
            unsigned int c = g_hist16[base + b];
            if (cum + c >= kneed) { digit = base + b; nk = kneed - cum; break; }
            cum += c;
        }
        g_state[0] = (g_state[0] << 16) | digit;
        g_state[1] = nk;
    }
    if (zero_after) {
        __syncthreads();
        for (int idx = t; idx < 65536; idx += 1024) g_hist16[idx] = 0u;
    }
}

__global__ __launch_bounds__(256) void topk_compact()
{
    const int i = blockIdx.x*256 + threadIdx.x;
    unsigned int key = __float_as_uint(g_scores[i]);
    unsigned int T = g_state[0];
    if (key >= T) {
        unsigned int pos = atomicAdd(&g_selcnt, 1u);
        if (pos < SORT_N)
            g_sel[pos] = ((unsigned long long)(~key) << 32) | (unsigned int)i;
    }
}

// ---------------- K4: hierarchical bitonic sort (regs/shfl/smem) + fused prep ----
__global__ __launch_bounds__(1024) void topk_sort()
{
    extern __shared__ unsigned long long S[];
    const int t = threadIdx.x;
    unsigned long long r[8];
#pragma unroll
    for (int e = 0; e < 8; e++) r[e] = g_sel[t*8 + e];

    for (unsigned int k = 2; k <= SORT_N; k <<= 1) {
        for (unsigned int j = k >> 1; j >= 256; j >>= 1) {
#pragma unroll
            for (int e = 0; e < 8; e++) S[t*8 + e] = r[e];
            __syncthreads();
#pragma unroll
            for (int e = 0; e < 8; e++) {
                const int i = t*8 + e;
                const unsigned long long p = S[i ^ j];
                const bool up = ((i & k) == 0);
                const bool lower = ((i & j) == 0);
                const unsigned long long mn = r[e] < p ? r[e] : p;
                const unsigned long long mx = r[e] < p ? p : r[e];
                r[e] = (up == lower) ? mn : mx;
            }
            __syncthreads();
        }
        for (unsigned int j = ((k>>1) < 128u ? (k>>1) : 128u); j >= 8; j >>= 1) {
            const int ls = (int)(j >> 3);
            const bool lowthread = ((t & ls) == 0);
#pragma unroll
            for (int e = 0; e < 8; e++) {
                const unsigned long long p = __shfl_xor_sync(0xffffffffu, r[e], ls);
                const int i = t*8 + e;
                const bool up = ((i & k) == 0);
                const unsigned long long mn = r[e] < p ? r[e] : p;
                const unsigned long long mx = r[e] < p ? p : r[e];
                r[e] = (up == lowthread) ? mn : mx;
            }
        }
        for (unsigned int j = ((k>>1) < 4u ? (k>>1) : 4u); j >= 1; j >>= 1) {
#pragma unroll
            for (int e = 0; e < 8; e++) {
                if ((e & (int)j) == 0) {
                    const int i = t*8 + e;
                    const bool up = ((i & k) == 0);
                    const unsigned long long a = r[e], b = r[e | (int)j];
                    if ((a > b) == up) { r[e] = b; r[e | (int)j] = a; }
                }
            }
        }
    }

#pragma unroll
    for (int e = 0; e < 8; e++) {
        const int p = t*8 + e;
        if (p < PRE_K) {
            const unsigned long long sel = r[e];
            const unsigned int idx = (unsigned int)(sel & 0xffffffffull);
            const unsigned int kb = ~(unsigned int)(sel >> 32);
            float x1 = g_props[idx*4+0], y1 = g_props[idx*4+1];
            float x2 = g_props[idx*4+2], y2 = g_props[idx*4+3];
            x1 = fminf(fmaxf(x1, 0.f), IMSZ);
            y1 = fminf(fmaxf(y1, 0.f), IMSZ);
            x2 = fminf(fmaxf(x2, 0.f), IMSZ);
            y2 = fminf(fmaxf(y2, 0.f), IMSZ);
            g_b6[p*4+0] = x1; g_b6[p*4+1] = y1; g_b6[p*4+2] = x2; g_b6[p*4+3] = y2;
            g_s6[p] = __uint_as_float(kb);
            g_valid[p] = ((x2 - x1) >= 16.f && (y2 - y1) >= 16.f) ? 1 : 0;
        }
    }
}

// ---------------- K5: NMS suppression bitmask (upper triangle only) ----------------
__global__ __launch_bounds__(64) void nms_mask_kernel()
{
    const int rb = blockIdx.x, cb = blockIdx.y;
    if (cb < rb) return;
    const int tid = threadIdx.x;
    __shared__ float cbx1[64], cby1[64], cbx2[64], cby2[64];
    const int j0 = cb*64;
    {
        int j = j0 + tid;
        float a=0,b=0,c=0,d=0;
        if (j < PRE_K) { a=g_b6[j*4+0]; b=g_b6[j*4+1]; c=g_b6[j*4+2]; d=g_b6[j*4+3]; }
        cbx1[tid]=a; cby1[tid]=b; cbx2[tid]=c; cby2[tid]=d;
    }
    __syncthreads();
    const int i = rb*64 + tid;
    if (i >= PRE_K) return;

    const float ix1 = g_b6[i*4+0], iy1 = g_b6[i*4+1];
    const float ix2 = g_b6[i*4+2], iy2 = g_b6[i*4+3];
    const float ai = (ix2-ix1)*(iy2-iy1);
    unsigned long long bits = 0ull;
#pragma unroll 4
    for (int jj = 0; jj < 64; jj++) {
        const int j = j0 + jj;
        if (j <= i || j >= PRE_K) continue;
        float xx1 = fmaxf(ix1, cbx1[jj]);
        float yy1 = fmaxf(iy1, cby1[jj]);
        float xx2 = fminf(ix2, cbx2[jj]);
        float yy2 = fminf(iy2, cby2[jj]);
        float inter = fmaxf(xx2-xx1, 0.f) * fmaxf(yy2-yy1, 0.f);
        float aj = (cbx2[jj]-cbx1[jj])*(cby2[jj]-cby1[jj]);
        float iou = inter / (ai + aj - inter);
        if (iou > 0.7f) bits |= (1ull << jj);
    }
    g_mask[(size_t)i*NWORDS + cb] = bits;
}

// ---------------- K6: greedy serial scan, early-exit @300 keeps, direct output ----
#define PF 16
__global__ __launch_bounds__(32) void nms_scan_out(float* __restrict__ out)
{
    const int l = threadIdx.x;
    __shared__ int list[POST_K];

    for (int k = l; k < POST_K*5; k += 32) out[k] = 0.f;

    unsigned long long rem0 = 0ull, rem1 = 0ull, rem2 = 0ull;
#pragma unroll
    for (int s = 0; s < 3; s++) {
        int w = l + 32*s;
        unsigned long long v = 0ull;
        if (w < NWORDS) {
            int base = w*64;
            int lim = (PRE_K - base) < 64 ? (PRE_K - base) : 64;
            for (int b = 0; b < lim; b++)
                if (!g_valid[base + b]) v |= (1ull << b);
        }
        if (s == 0) rem0 = v; else if (s == 1) rem1 = v; else rem2 = v;
    }

    unsigned long long pa[PF], pb[PF], pc[PF];
#pragma unroll
    for (int u = 0; u < PF; u++) {
        const unsigned long long* row = g_mask + (size_t)u*NWORDS;
        pa[u] = row[l];
        pb[u] = (l + 32 < NWORDS) ? row[l+32] : 0ull;
        pc[u] = (l + 64 < NWORDS) ? row[l+64] : 0ull;
    }

    int kept = 0;
    for (int i0 = 0; i0 < PRE_K; i0 += PF) {
#pragma unroll
        for (int u = 0; u < PF; u++) {
            const int i = i0 + u;
            const int w = i >> 6;
            const int src = w & 31;
            const int slot = w >> 5;
            unsigned long long my = (slot == 0) ? rem0 : ((slot == 1) ? rem1 : rem2);
            unsigned long long word = __shfl_sync(0xffffffffu, my, src);
            const bool sup = (word >> (i & 63)) & 1ull;
            if (!sup) {
                rem0 |= pa[u]; rem1 |= pb[u]; rem2 |= pc[u];
                if (l == 0) list[kept] = i;
                kept++;
                if (kept == POST_K) goto done;
            }
            const int nx = i + PF;
            if (nx < PRE_K) {
                const unsigned long long* row = g_mask + (size_t)nx*NWORDS;
                const int w0 = nx >> 6;
                pa[u] = (l >= w0) ? row[l] : 0ull;
                pb[u] = (l+32 >= w0 && l+32 < NWORDS) ? row[l+32] : 0ull;
                pc[u] = (l+64 >= w0 && l+64 < NWORDS) ? row[l+64] : 0ull;
            }
        }
    }
done:
    __syncwarp();
    for (int rI = l; rI < kept; rI += 32) {
        const int i = list[rI];
        out[rI*5+0] = g_b6[i*4+0];
        out[rI*5+1] = g_b6[i*4+1];
        out[rI*5+2] = g_b6[i*4+2];
        out[rI*5+3] = g_b6[i*4+3];
        out[rI*5+4] = g_s6[i];
    }
}

// ---------------- launch ----------------
extern "C" void kernel_launch(void* const* d_in, const int* in_sizes, int n_in,
                              void* d_out, int out_size)
{
    (void)in_sizes; (void)n_in; (void)out_size;
    const float* feat = (const float*)d_in[1];
    const float* cw   = (const float*)d_in[2];
    const float* cb   = (const float*)d_in[3];
    const float* clsw = (const float*)d_in[4];
    const float* clsb = (const float*)d_in[5];
    const float* bw   = (const float*)d_in[6];
    const float* bb   = (const float*)d_in[7];
    float* out = (float*)d_out;

    // launches 1..5: independent init (puts conv3 at launch #6 for ncu -s 5 -c 1)
    init_hist<<<16, 1024>>>(0);
    init_hist<<<16, 1024>>>(1);
    init_hist<<<16, 1024>>>(2);
    init_hist<<<16, 1024>>>(3);
    init_sel<<<8, 1024>>>();

    conv3_kernel<<<dim3(256, 4), 128>>>(feat, cw, cb);
    head_kernel<<<256, 256>>>(clsw, clsb, bw, bb);

    hist16_kernel<<<576, 256>>>(0);
    sel16_kernel<<<1, 1024>>>(1);
    hist16_kernel<<<576, 256>>>(1);
    sel16_kernel<<<1, 1024>>>(0);
    topk_compact<<<576, 256>>>();

    cudaFuncSetAttribute(topk_sort, cudaFuncAttributeMaxDynamicSharedMemorySize, 65536);
    topk_sort<<<1, 1024, 65536>>>();

    nms_mask_kernel<<<dim3(94, 94), 64>>>();
    nms_scan_out<<<1, 32>>>(out);
}